// round 16
// baseline (speedup 1.0000x reference)
#include <cuda_runtime.h>
#include <cuda_fp16.h>

#define NN 8192
#define CC 16
#define KAUG 24          // halves per augmented row (16 used), 48B stride
#define UPAD 136
#define THREADS 256
#define NB 64            // 128-row tiles per dimension

// ---------------- device scratch ----------------
__device__ __align__(16) __half g_Aaug[NN * KAUG];
__device__ __align__(16) __half g_Baug[NN * KAUG];
__device__ __align__(16) __half g_UT[64 * CC * 128];   // [tile][c][j]

// smem layout (in halves)
#define SA   0        // 128*24 = 3072
#define SB   3072     // 128*24 = 3072
#define SUJ  6144     // 16*136 = 2176
#define SUI  8320     // 16*136 = 2176
#define SW   10496    // 128*136 = 17408 (W tile, 272B row stride)
#define SMEM_HALVES 27904
#define SMEM_BYTES (SMEM_HALVES * 2)   // 55808 B

// ---------------- helpers ----------------
__device__ __forceinline__ unsigned s2u(const void* p) {
    return (unsigned)__cvta_generic_to_shared(p);
}
__device__ __forceinline__ unsigned ex2h(unsigned x) {
    unsigned y; asm("ex2.approx.f16x2 %0, %1;" : "=r"(y) : "r"(x)); return y;
}
__device__ __forceinline__ unsigned cvt2h(float hi, float lo) {
    unsigned d; asm("cvt.rn.f16x2.f32 %0, %1, %2;" : "=r"(d) : "f"(hi), "f"(lo)); return d;
}
__device__ __forceinline__ void ldsm4(unsigned& r0, unsigned& r1, unsigned& r2, unsigned& r3, unsigned a) {
    asm volatile("ldmatrix.sync.aligned.m8n8.x4.shared.b16 {%0,%1,%2,%3}, [%4];"
                 : "=r"(r0), "=r"(r1), "=r"(r2), "=r"(r3) : "r"(a));
}
__device__ __forceinline__ void ldsm4t(unsigned& r0, unsigned& r1, unsigned& r2, unsigned& r3, unsigned a) {
    asm volatile("ldmatrix.sync.aligned.m8n8.x4.trans.shared.b16 {%0,%1,%2,%3}, [%4];"
                 : "=r"(r0), "=r"(r1), "=r"(r2), "=r"(r3) : "r"(a));
}
__device__ __forceinline__ void sts32(unsigned a, unsigned v) {
    asm volatile("st.shared.u32 [%0], %1;" :: "r"(a), "r"(v));
}
__device__ __forceinline__ void mma16816(float* c, unsigned a0, unsigned a1, unsigned a2, unsigned a3,
                                         unsigned b0, unsigned b1) {
    asm volatile("mma.sync.aligned.m16n8k16.row.col.f32.f16.f16.f32 "
                 "{%0,%1,%2,%3}, {%4,%5,%6,%7}, {%8,%9}, {%0,%1,%2,%3};"
                 : "+f"(c[0]), "+f"(c[1]), "+f"(c[2]), "+f"(c[3])
                 : "r"(a0), "r"(a1), "r"(a2), "r"(a3), "r"(b0), "r"(b1));
}
__device__ __forceinline__ void cp16(unsigned saddr, const void* g) {
    asm volatile("cp.async.ca.shared.global [%0], [%1], 16;" :: "r"(saddr), "l"(g));
}
#define CP_COMMIT() asm volatile("cp.async.commit_group;" ::: "memory")

// ---------------- pre-kernel (R11 version): 64 blocks, 128 rows each ----------------
__global__ __launch_bounds__(256) void lg_pre_kernel(const float* __restrict__ U,
                                                     const float* __restrict__ ref,
                                                     float* __restrict__ out) {
    __shared__ __half sUh[128 * 17];
    const int b = blockIdx.x;
    const int tid = threadIdx.x;

#pragma unroll
    for (int k = 0; k < 8; k++) {
        int idx = k * 256 + tid;
        float f = U[b * 2048 + idx];
        out[b * 2048 + idx] = -f;
        sUh[(idx >> 4) * 17 + (idx & 15)] = __float2half_rn(f);
    }
    __syncthreads();

    unsigned* gUTu = (unsigned*)g_UT;
#pragma unroll
    for (int k = 0; k < 4; k++) {
        int w = k * 256 + tid;
        int c  = w >> 6;
        int j2 = w & 63;
        __half h0 = sUh[(2 * j2) * 17 + c];
        __half h1 = sUh[(2 * j2 + 1) * 17 + c];
        unsigned v = (unsigned)__half_as_ushort(h0) | ((unsigned)__half_as_ushort(h1) << 16);
        gUTu[((size_t)b * 16 + c) * 64 + j2] = v;
    }

    if (tid < 128) {
        const int i = b * 128 + tid;
        const float SC = 1.2011224087864498f;  // sqrt(log2 e)
        float rs[5], ss = 0.f;
#pragma unroll
        for (int k = 0; k < 5; k++) { rs[k] = ref[i * 5 + k] * SC; ss += rs[k] * rs[k]; }
        float c = -0.5f * ss;
        unsigned short rh[5], rl[5], chh, cll;
#pragma unroll
        for (int k = 0; k < 5; k++) {
            __half hh = __float2half_rn(rs[k]);
            rh[k] = __half_as_ushort(hh);
            rl[k] = __half_as_ushort(__float2half_rn(rs[k] - __half2float(hh)));
        }
        {
            __half hc = __float2half_rn(c);
            chh = __half_as_ushort(hc);
            cll = __half_as_ushort(__float2half_rn(c - __half2float(hc)));
        }
        const unsigned short ONE = 0x3C00;
        unsigned short A[KAUG], B[KAUG];
#pragma unroll
        for (int k = 0; k < KAUG; k++) { A[k] = 0; B[k] = 0; }
        // A: [rh(0-4), rl(5-9), chh, cll, 1, 1, 0, 0]
        // B: [rh(0-4), rh(5-9), 1, 1, chh, cll, 0, 0]
#pragma unroll
        for (int k = 0; k < 5; k++) { A[k] = rh[k]; A[5 + k] = rl[k]; }
        A[10] = chh; A[11] = cll; A[12] = ONE; A[13] = ONE;
#pragma unroll
        for (int k = 0; k < 5; k++) { B[k] = rh[k]; B[5 + k] = rh[k]; }
        B[10] = ONE; B[11] = ONE; B[12] = chh; B[13] = cll;
        uint4* gA = (uint4*)(g_Aaug + (size_t)i * KAUG);
        uint4* gB = (uint4*)(g_Baug + (size_t)i * KAUG);
#pragma unroll
        for (int q = 0; q < 3; q++) {
            gA[q] = ((const uint4*)A)[q];
            gB[q] = ((const uint4*)B)[q];
        }
    }
}

// ---------------- main kernel: symmetric (128 x 128) tile pairs, m16/warp, occ 4 ----------------
__global__ __launch_bounds__(THREADS, 4) void lg_main_kernel(float* __restrict__ out) {
    extern __shared__ __align__(16) __half smem[];

    const int tid = threadIdx.x;
    const int w = tid >> 5;
    const int l = tid & 31;

    // triangular decode: pairs (bi, bj) with bi <= bj
    int bi = 0, rem = blockIdx.x;
    while (rem >= NB - bi) { rem -= NB - bi; bi++; }
    const int bj = bi + rem;

    const unsigned sAb  = s2u(smem + SA);
    const unsigned sBb  = s2u(smem + SB);
    const unsigned sUJb = s2u(smem + SUJ);
    const unsigned sUIb = s2u(smem + SUI);
    const unsigned sWb  = s2u(smem + SW);

    // ---- prologue loads ----
    {
        const char* gA = (const char*)(g_Aaug) + (size_t)bi * 128 * KAUG * 2;
        for (int k = tid; k < 384; k += THREADS) cp16(sAb + k * 16, gA + k * 16);
        const char* gB = (const char*)(g_Baug) + (size_t)bj * 128 * KAUG * 2;
        for (int k = tid; k < 384; k += THREADS) cp16(sBb + k * 16, gB + k * 16);
        const char* gUJ = (const char*)(g_UT) + (size_t)bj * CC * 256;
        for (int k = tid; k < 256; k += THREADS) {
            int row = k >> 4, q = k & 15;
            cp16(sUJb + row * (UPAD * 2) + q * 16, gUJ + k * 16);
        }
        const char* gUI = (const char*)(g_UT) + (size_t)bi * CC * 256;
        for (int k = tid; k < 256; k += THREADS) {
            int row = k >> 4, q = k & 15;
            cp16(sUIb + row * (UPAD * 2) + q * 16, gUI + k * 16);
        }
        CP_COMMIT();
    }

    // lane address pieces
    const int lrowB = ((l >> 4) & 1) * 8 + (l & 7);
    const int lkB   = ((l >> 3) & 1) * 16;
    const int lrowA = ((l >> 3) & 1) * 8 + (l & 7);
    const int lkA   = ((l >> 4) & 1) * 16;
    const int g  = l >> 2;
    const int tq = l & 3;

    float oa[2][4];
#pragma unroll
    for (int nb = 0; nb < 2; nb++)
#pragma unroll
        for (int q = 0; q < 4; q++) oa[nb][q] = 0.f;

    asm volatile("cp.async.wait_group 0;" ::: "memory");
    __syncthreads();

    // A fragment: this warp's m16 strip (rows 16w..16w+15)
    unsigned aF[4];
    ldsm4(aF[0], aF[1], aF[2], aF[3], sAb + (w * 16 + lrowA) * (KAUG * 2) + lkA);

    const unsigned swSts = sWb + (w * 16 + g) * 272 + tq * 4;

#pragma unroll
    for (int p = 0; p < 8; p++) {
        unsigned b0, b1, b2, b3;
        ldsm4(b0, b1, b2, b3, sBb + (p * 16 + lrowB) * (KAUG * 2) + lkB);
        unsigned u0, u1, u2, u3;
        ldsm4(u0, u1, u2, u3, sUJb + lrowB * (UPAD * 2) + p * 32 + lkB);

        float s0[4] = {0.f, 0.f, 0.f, 0.f};
        float s1[4] = {0.f, 0.f, 0.f, 0.f};
        mma16816(s0, aF[0], aF[1], aF[2], aF[3], b0, b1);
        mma16816(s1, aF[0], aF[1], aF[2], aF[3], b2, b3);
        unsigned w0 = ex2h(cvt2h(s0[1], s0[0]));   // rows g,    j [16p,16p+8)
        unsigned w1 = ex2h(cvt2h(s0[3], s0[2]));   // rows g+8,  j [16p,16p+8)
        unsigned w2 = ex2h(cvt2h(s1[1], s1[0]));   // rows g,    j [16p+8,16p+16)
        unsigned w3 = ex2h(cvt2h(s1[3], s1[2]));   // rows g+8,  j [16p+8,16p+16)

        // stage W to smem for the transposed pass
        {
            unsigned a0 = swSts + p * 32;
            sts32(a0,             w0);
            sts32(a0 + 8 * 272,   w1);
            sts32(a0 + 16,        w2);
            sts32(a0 + 8 * 272 + 16, w3);
        }

        // GEMM2a: out_I strip += W * U_J
        mma16816(oa[0], w0, w1, w2, w3, u0, u1);
        mma16816(oa[1], w0, w1, w2, w3, u2, u3);
    }

    __syncthreads();

    // ---- GEMM2b (off-diagonal only): out_J strip += W^T * U_I ----
    if (bi != bj) {
        float ob[2][4];
#pragma unroll
        for (int nb = 0; nb < 2; nb++)
#pragma unroll
            for (int q = 0; q < 4; q++) ob[nb][q] = 0.f;

        const int lr = l & 7;
        const int grp = l >> 3;
        // lane source address for ldsm.trans: W[i = 16k + (grp&2?8:0) + lr][j = 16w + (grp&1?8:0)]
        const unsigned swLd = sWb + (((grp & 2) ? 8 : 0) + lr) * 272 + (w * 16 + ((grp & 1) ? 8 : 0)) * 2;

#pragma unroll
        for (int k = 0; k < 8; k++) {
            unsigned a0, a1, a2, a3;
            ldsm4t(a0, a1, a2, a3, swLd + k * 16 * 272);
            unsigned u0, u1, u2, u3;
            ldsm4(u0, u1, u2, u3, sUIb + lrowB * (UPAD * 2) + k * 32 + lkB);
            mma16816(ob[0], a0, a1, a2, a3, u0, u1);
            mma16816(ob[1], a0, a1, a2, a3, u2, u3);
        }

        const int j0 = bj * 128 + w * 16 + g;
#pragma unroll
        for (int nb = 0; nb < 2; nb++) {
            const int col = nb * 8 + tq * 2;
            atomicAdd(&out[j0 * CC + col],           ob[nb][0]);
            atomicAdd(&out[j0 * CC + col + 1],       ob[nb][1]);
            atomicAdd(&out[(j0 + 8) * CC + col],     ob[nb][2]);
            atomicAdd(&out[(j0 + 8) * CC + col + 1], ob[nb][3]);
        }
    }

    // ---- GEMM2a epilogue ----
    const int i0 = bi * 128 + w * 16 + g;
#pragma unroll
    for (int nb = 0; nb < 2; nb++) {
        const int col = nb * 8 + tq * 2;
        atomicAdd(&out[i0 * CC + col],           oa[nb][0]);
        atomicAdd(&out[i0 * CC + col + 1],       oa[nb][1]);
        atomicAdd(&out[(i0 + 8) * CC + col],     oa[nb][2]);
        atomicAdd(&out[(i0 + 8) * CC + col + 1], oa[nb][3]);
    }
}

extern "C" void kernel_launch(void* const* d_in, const int* in_sizes, int n_in,
                              void* d_out, int out_size) {
    const float* U   = (const float*)d_in[0];
    const float* ref = (const float*)d_in[1];
    float* out = (float*)d_out;

    static int attrSet = 0;
    if (!attrSet) {
        cudaFuncSetAttribute(lg_main_kernel, cudaFuncAttributeMaxDynamicSharedMemorySize, SMEM_BYTES);
        attrSet = 1;
    }

    lg_pre_kernel<<<64, 256>>>(U, ref, out);

    lg_main_kernel<<<NB * (NB + 1) / 2, THREADS, SMEM_BYTES>>>(out);
}

// round 17
// speedup vs baseline: 1.3319x; 1.3319x over previous
#include <cuda_runtime.h>
#include <cuda_fp16.h>

#define NN 8192
#define CC 16
#define KAUG 24          // halves per augmented row (16 used), 48B stride
#define UPAD 136
#define THREADS 256
#define ITILE 256
#define NTOT 2048        // 32 i-tiles x 64 j-tiles
#define GRID 592         // 148 SMs x occ 4 -> single persistent wave

// ---------------- device scratch ----------------
__device__ __align__(16) __half g_Aaug[NN * KAUG];
__device__ __align__(16) __half g_Baug[NN * KAUG];
__device__ __align__(16) __half g_UT[64 * CC * 128];   // [tile][c][j]

// per-buffer smem layout (in halves)
#define SA  0                      // 256*24 = 6144
#define SB  6144                   // 128*24 = 3072
#define SU  9216                   // 16*136 = 2176
#define BUFH 11392                 // halves per buffer
#define SMEM_BYTES (2 * BUFH * 2)  // 45568 B

// ---------------- helpers ----------------
__device__ __forceinline__ unsigned s2u(const void* p) {
    return (unsigned)__cvta_generic_to_shared(p);
}
__device__ __forceinline__ unsigned ex2h(unsigned x) {
    unsigned y; asm("ex2.approx.f16x2 %0, %1;" : "=r"(y) : "r"(x)); return y;
}
__device__ __forceinline__ unsigned cvt2h(float hi, float lo) {
    unsigned d; asm("cvt.rn.f16x2.f32 %0, %1, %2;" : "=r"(d) : "f"(hi), "f"(lo)); return d;
}
__device__ __forceinline__ void ldsm4(unsigned& r0, unsigned& r1, unsigned& r2, unsigned& r3, unsigned a) {
    asm volatile("ldmatrix.sync.aligned.m8n8.x4.shared.b16 {%0,%1,%2,%3}, [%4];"
                 : "=r"(r0), "=r"(r1), "=r"(r2), "=r"(r3) : "r"(a));
}
__device__ __forceinline__ void mma16816(float* c, unsigned a0, unsigned a1, unsigned a2, unsigned a3,
                                         unsigned b0, unsigned b1) {
    asm volatile("mma.sync.aligned.m16n8k16.row.col.f32.f16.f16.f32 "
                 "{%0,%1,%2,%3}, {%4,%5,%6,%7}, {%8,%9}, {%0,%1,%2,%3};"
                 : "+f"(c[0]), "+f"(c[1]), "+f"(c[2]), "+f"(c[3])
                 : "r"(a0), "r"(a1), "r"(a2), "r"(a3), "r"(b0), "r"(b1));
}
__device__ __forceinline__ void cp16(unsigned saddr, const void* g) {
    asm volatile("cp.async.ca.shared.global [%0], [%1], 16;" :: "r"(saddr), "l"(g));
}
#define CP_COMMIT() asm volatile("cp.async.commit_group;" ::: "memory")

// ---------------- pre-kernel (unchanged): 64 blocks, 128 rows each ----------------
__global__ __launch_bounds__(256) void lg_pre_kernel(const float* __restrict__ U,
                                                     const float* __restrict__ ref,
                                                     float* __restrict__ out) {
    __shared__ __half sUh[128 * 17];
    const int b = blockIdx.x;
    const int tid = threadIdx.x;

#pragma unroll
    for (int k = 0; k < 8; k++) {
        int idx = k * 256 + tid;
        float f = U[b * 2048 + idx];
        out[b * 2048 + idx] = -f;
        sUh[(idx >> 4) * 17 + (idx & 15)] = __float2half_rn(f);
    }
    __syncthreads();

    unsigned* gUTu = (unsigned*)g_UT;
#pragma unroll
    for (int k = 0; k < 4; k++) {
        int w = k * 256 + tid;
        int c  = w >> 6;
        int j2 = w & 63;
        __half h0 = sUh[(2 * j2) * 17 + c];
        __half h1 = sUh[(2 * j2 + 1) * 17 + c];
        unsigned v = (unsigned)__half_as_ushort(h0) | ((unsigned)__half_as_ushort(h1) << 16);
        gUTu[((size_t)b * 16 + c) * 64 + j2] = v;
    }

    if (tid < 128) {
        const int i = b * 128 + tid;
        const float SC = 1.2011224087864498f;  // sqrt(log2 e)
        float rs[5], ss = 0.f;
#pragma unroll
        for (int k = 0; k < 5; k++) { rs[k] = ref[i * 5 + k] * SC; ss += rs[k] * rs[k]; }
        float c = -0.5f * ss;
        unsigned short rh[5], rl[5], chh, cll;
#pragma unroll
        for (int k = 0; k < 5; k++) {
            __half hh = __float2half_rn(rs[k]);
            rh[k] = __half_as_ushort(hh);
            rl[k] = __half_as_ushort(__float2half_rn(rs[k] - __half2float(hh)));
        }
        {
            __half hc = __float2half_rn(c);
            chh = __half_as_ushort(hc);
            cll = __half_as_ushort(__float2half_rn(c - __half2float(hc)));
        }
        const unsigned short ONE = 0x3C00;
        unsigned short A[KAUG], B[KAUG];
#pragma unroll
        for (int k = 0; k < KAUG; k++) { A[k] = 0; B[k] = 0; }
        // A: [rh(0-4), rl(5-9), chh, cll, 1, 1, 0, 0]
        // B: [rh(0-4), rh(5-9), 1, 1, chh, cll, 0, 0]
#pragma unroll
        for (int k = 0; k < 5; k++) { A[k] = rh[k]; A[5 + k] = rl[k]; }
        A[10] = chh; A[11] = cll; A[12] = ONE; A[13] = ONE;
#pragma unroll
        for (int k = 0; k < 5; k++) { B[k] = rh[k]; B[5 + k] = rh[k]; }
        B[10] = ONE; B[11] = ONE; B[12] = chh; B[13] = cll;
        uint4* gA = (uint4*)(g_Aaug + (size_t)i * KAUG);
        uint4* gB = (uint4*)(g_Baug + (size_t)i * KAUG);
#pragma unroll
        for (int q = 0; q < 3; q++) {
            gA[q] = ((const uint4*)A)[q];
            gB[q] = ((const uint4*)B)[q];
        }
    }
}

// ---------------- main kernel: persistent CTAs, double-buffered tiles ----------------
__global__ __launch_bounds__(THREADS, 4) void lg_main_kernel(float* __restrict__ out) {
    extern __shared__ __align__(16) __half smem[];
    const unsigned sbase = s2u(smem);

    const int tid = threadIdx.x;
    const int w = tid >> 5;
    const int l = tid & 31;

    // lane address pieces (constant across tiles)
    const int lrowB = ((l >> 4) & 1) * 8 + (l & 7);
    const int lkB   = ((l >> 3) & 1) * 16;
    const int lrowA = ((l >> 3) & 1) * 8 + (l & 7);
    const int lkA   = ((l >> 4) & 1) * 16;
    const int g  = l >> 2;
    const int tq = l & 3;

    // tile loader: t -> buffer bf
    auto load_tile = [&](int t, int bf) {
        const int bx = t >> 6;
        const int by = t & 63;
        const unsigned base = sbase + (unsigned)bf * (BUFH * 2);
        const char* gA = (const char*)(g_Aaug) + (size_t)bx * ITILE * KAUG * 2;
        for (int k = tid; k < 768; k += THREADS) cp16(base + SA * 2 + k * 16, gA + k * 16);
        const char* gB = (const char*)(g_Baug) + (size_t)by * 128 * KAUG * 2;
        for (int k = tid; k < 384; k += THREADS) cp16(base + SB * 2 + k * 16, gB + k * 16);
        const char* gU = (const char*)(g_UT) + (size_t)by * CC * 256;
        for (int k = tid; k < 256; k += THREADS) {
            int row = k >> 4, q = k & 15;
            cp16(base + SU * 2 + row * (UPAD * 2) + q * 16, gU + k * 16);
        }
    };

    int t = blockIdx.x;
    int bf = 0;
    if (t < NTOT) { load_tile(t, 0); }
    CP_COMMIT();

    for (; t < NTOT; t += GRID) {
        const int tn = t + GRID;
        if (tn < NTOT) load_tile(tn, bf ^ 1);
        CP_COMMIT();
        asm volatile("cp.async.wait_group 1;" ::: "memory");
        __syncthreads();

        const unsigned base = sbase + (unsigned)bf * (BUFH * 2);
        const unsigned sAb = base + SA * 2;
        const unsigned sBb = base + SB * 2;
        const unsigned sUb = base + SU * 2;

        const int bx = t >> 6;

        float o0[2][4], o1[2][4];
#pragma unroll
        for (int nb = 0; nb < 2; nb++)
#pragma unroll
            for (int q = 0; q < 4; q++) { o0[nb][q] = 0.f; o1[nb][q] = 0.f; }

        unsigned aF0[4], aF1[4];
        const unsigned aAddr = sAb + (w * 32 + lrowA) * (KAUG * 2) + lkA;
        ldsm4(aF0[0], aF0[1], aF0[2], aF0[3], aAddr);
        ldsm4(aF1[0], aF1[1], aF1[2], aF1[3], aAddr + 16 * (KAUG * 2));

#pragma unroll
        for (int p = 0; p < 8; p++) {
            unsigned b0, b1, b2, b3;
            ldsm4(b0, b1, b2, b3, sBb + (p * 16 + lrowB) * (KAUG * 2) + lkB);
            unsigned u0, u1, u2, u3;
            ldsm4(u0, u1, u2, u3, sUb + lrowB * (UPAD * 2) + p * 32 + lkB);

            // m-block 0
            unsigned w00, w01, w02, w03;
            {
                float s0[4] = {0.f, 0.f, 0.f, 0.f};
                float s1[4] = {0.f, 0.f, 0.f, 0.f};
                mma16816(s0, aF0[0], aF0[1], aF0[2], aF0[3], b0, b1);
                mma16816(s1, aF0[0], aF0[1], aF0[2], aF0[3], b2, b3);
                w00 = ex2h(cvt2h(s0[1], s0[0]));
                w01 = ex2h(cvt2h(s0[3], s0[2]));
                w02 = ex2h(cvt2h(s1[1], s1[0]));
                w03 = ex2h(cvt2h(s1[3], s1[2]));
            }
            // m-block 1
            unsigned w10, w11, w12, w13;
            {
                float s0[4] = {0.f, 0.f, 0.f, 0.f};
                float s1[4] = {0.f, 0.f, 0.f, 0.f};
                mma16816(s0, aF1[0], aF1[1], aF1[2], aF1[3], b0, b1);
                mma16816(s1, aF1[0], aF1[1], aF1[2], aF1[3], b2, b3);
                w10 = ex2h(cvt2h(s0[1], s0[0]));
                w11 = ex2h(cvt2h(s0[3], s0[2]));
                w12 = ex2h(cvt2h(s1[1], s1[0]));
                w13 = ex2h(cvt2h(s1[3], s1[2]));
            }

            mma16816(o0[0], w00, w01, w02, w03, u0, u1);
            mma16816(o0[1], w00, w01, w02, w03, u2, u3);
            mma16816(o1[0], w10, w11, w12, w13, u0, u1);
            mma16816(o1[1], w10, w11, w12, w13, u2, u3);
        }

        // ---- epilogue for this tile ----
        const int i0 = bx * ITILE + w * 32 + g;
#pragma unroll
        for (int nb = 0; nb < 2; nb++) {
            const int col = nb * 8 + tq * 2;
            atomicAdd(&out[i0 * CC + col],            o0[nb][0]);
            atomicAdd(&out[i0 * CC + col + 1],        o0[nb][1]);
            atomicAdd(&out[(i0 + 8) * CC + col],      o0[nb][2]);
            atomicAdd(&out[(i0 + 8) * CC + col + 1],  o0[nb][3]);
            atomicAdd(&out[(i0 + 16) * CC + col],     o1[nb][0]);
            atomicAdd(&out[(i0 + 16) * CC + col + 1], o1[nb][1]);
            atomicAdd(&out[(i0 + 24) * CC + col],     o1[nb][2]);
            atomicAdd(&out[(i0 + 24) * CC + col + 1], o1[nb][3]);
        }

        __syncthreads();   // all reads of this buffer done before it is overwritten
        bf ^= 1;
    }
}

extern "C" void kernel_launch(void* const* d_in, const int* in_sizes, int n_in,
                              void* d_out, int out_size) {
    const float* U   = (const float*)d_in[0];
    const float* ref = (const float*)d_in[1];
    float* out = (float*)d_out;

    static int attrSet = 0;
    if (!attrSet) {
        cudaFuncSetAttribute(lg_main_kernel, cudaFuncAttributeMaxDynamicSharedMemorySize, SMEM_BYTES);
        attrSet = 1;
    }

    lg_pre_kernel<<<64, 256>>>(U, ref, out);

    lg_main_kernel<<<GRID, THREADS, SMEM_BYTES>>>(out);
}